// round 2
// baseline (speedup 1.0000x reference)
#include <cuda_runtime.h>
#include <mma.h>
#include <cstdint>

using namespace nvcuda;

// Problem constants
#define BB 4
#define SS 4096
#define DD 1024
#define MROWS (BB*SS)        // 16384
#define NPROJ 6144           // q|k|v|ar|ai|g
#define CHUNKS 64
#define CLEN 64              // SS / CHUNKS
#define EPS 1e-6f

// Column offsets inside the fused projection buffer
#define OFF_Q  0
#define OFF_K  1024
#define OFF_V  2048
#define OFF_AR 3072
#define OFF_AI 4096
#define OFF_G  5120

// ---------------- scratch (device globals, no allocations) ----------------
__device__ float g_xn[(size_t)MROWS * DD];       // 64 MB
__device__ float g_proj[(size_t)MROWS * NPROJ];  // 384 MB
__device__ float g_y[(size_t)MROWS * DD];        // 64 MB
__device__ float g_cAr[BB * CHUNKS * DD];
__device__ float g_cAi[BB * CHUNKS * DD];
__device__ float g_cHr[BB * CHUNKS * DD];
__device__ float g_cHi[BB * CHUNKS * DD];
__device__ float g_hinr[BB * CHUNKS * DD];
__device__ float g_hini[BB * CHUNKS * DD];

// ---------------- RMSNorm: x -> g_xn ----------------
__global__ void __launch_bounds__(256) rmsnorm_kernel(const float* __restrict__ x,
                                                      const float* __restrict__ scale) {
    int row = blockIdx.x;
    int tid = threadIdx.x;  // 256 threads, 4 elems each
    const float4* xr = (const float4*)(x + (size_t)row * DD);
    float4 v = xr[tid];
    float ss = v.x * v.x + v.y * v.y + v.z * v.z + v.w * v.w;
    #pragma unroll
    for (int o = 16; o; o >>= 1) ss += __shfl_xor_sync(0xffffffffu, ss, o);
    __shared__ float sbuf[8];
    if ((tid & 31) == 0) sbuf[tid >> 5] = ss;
    __syncthreads();
    if (tid < 8) {
        float t = sbuf[tid];
        #pragma unroll
        for (int o = 4; o; o >>= 1) t += __shfl_xor_sync(0xffu, t, o);
        if (tid == 0) sbuf[0] = t;
    }
    __syncthreads();
    float inv = rsqrtf(sbuf[0] * (1.0f / DD) + EPS);
    float4 sc = ((const float4*)scale)[tid];
    float4 o;
    o.x = v.x * inv * sc.x;
    o.y = v.y * inv * sc.y;
    o.z = v.z * inv * sc.z;
    o.w = v.w * inv * sc.w;
    ((float4*)(g_xn + (size_t)row * DD))[tid] = o;
}

// ---------------- tf32 wmma GEMM: C[M,N] = A[M,K] @ W[K,N] ----------------
#define BM 128
#define BN 64
#define BK 32
#define LDA_S 36
#define LDB_S 68

__global__ void __launch_bounds__(256) gemm_tf32(
    const float* __restrict__ A, int lda,
    const float* __restrict__ W, int ldw,
    float* __restrict__ C, int ldc, int Kdim)
{
    __shared__ float As[BM * LDA_S];
    __shared__ float Bs[BK * LDB_S];
    int tid = threadIdx.x;
    int m0 = blockIdx.y * BM;
    int n0 = blockIdx.x * BN;
    int warp = tid >> 5;
    int wm = warp & 3;       // 0..3  (rows within block tile, 32 rows each)
    int wn = warp >> 2;      // 0..1  (cols, 32 cols each)

    wmma::fragment<wmma::accumulator, 16, 16, 8, float> acc[2][2];
    #pragma unroll
    for (int i = 0; i < 2; i++)
        #pragma unroll
        for (int j = 0; j < 2; j++)
            wmma::fill_fragment(acc[i][j], 0.0f);

    for (int k0 = 0; k0 < Kdim; k0 += BK) {
        // load A tile: BM x BK (float4)
        #pragma unroll
        for (int i = tid; i < BM * BK / 4; i += 256) {
            int r = i >> 3, c4 = i & 7;
            float4 v = *(const float4*)(A + (size_t)(m0 + r) * lda + k0 + c4 * 4);
            *(float4*)(As + r * LDA_S + c4 * 4) = v;
        }
        // load B tile: BK x BN (float4)
        #pragma unroll
        for (int i = tid; i < BK * BN / 4; i += 256) {
            int r = i >> 4, c4 = i & 15;
            float4 v = *(const float4*)(W + (size_t)(k0 + r) * ldw + n0 + c4 * 4);
            *(float4*)(Bs + r * LDB_S + c4 * 4) = v;
        }
        __syncthreads();

        #pragma unroll
        for (int kk = 0; kk < BK; kk += 8) {
            wmma::fragment<wmma::matrix_a, 16, 16, 8, wmma::precision::tf32, wmma::row_major> af[2];
            wmma::fragment<wmma::matrix_b, 16, 16, 8, wmma::precision::tf32, wmma::row_major> bf[2];
            #pragma unroll
            for (int i = 0; i < 2; i++) {
                wmma::load_matrix_sync(af[i], As + (wm * 32 + i * 16) * LDA_S + kk, LDA_S);
                #pragma unroll
                for (int t = 0; t < af[i].num_elements; t++)
                    af[i].x[t] = wmma::__float_to_tf32(af[i].x[t]);
            }
            #pragma unroll
            for (int j = 0; j < 2; j++) {
                wmma::load_matrix_sync(bf[j], Bs + kk * LDB_S + wn * 32 + j * 16, LDB_S);
                #pragma unroll
                for (int t = 0; t < bf[j].num_elements; t++)
                    bf[j].x[t] = wmma::__float_to_tf32(bf[j].x[t]);
            }
            #pragma unroll
            for (int i = 0; i < 2; i++)
                #pragma unroll
                for (int j = 0; j < 2; j++)
                    wmma::mma_sync(acc[i][j], af[i], bf[j], acc[i][j]);
        }
        __syncthreads();
    }

    #pragma unroll
    for (int i = 0; i < 2; i++)
        #pragma unroll
        for (int j = 0; j < 2; j++)
            wmma::store_matrix_sync(
                C + (size_t)(m0 + wm * 32 + i * 16) * ldc + n0 + wn * 32 + j * 16,
                acc[i][j], ldc, wmma::mem_row_major);
}

// ---------------- complex gate helper ----------------
__device__ __forceinline__ void make_ac(float ar, float ai, float& acr, float& aci) {
    // a_c = sigmoid(|a|) * exp(i*angle(a))
    float r = sqrtf(ar * ar + ai * ai);
    float s = 1.0f / (1.0f + __expf(-r));
    if (r > 0.0f) {
        float inv = s / r;
        acr = ar * inv;
        aci = ai * inv;
    } else {
        acr = s;   // angle(0) = 0 -> a_c = sigmoid(0)
        aci = 0.0f;
    }
}

// ---------------- scan pass 1: per-chunk summaries ----------------
__global__ void __launch_bounds__(256) scan_pass1() {
    int d = blockIdx.x * 256 + threadIdx.x;
    int c = blockIdx.y;
    int b = blockIdx.z;
    const float* base = g_proj + (size_t)(b * SS + c * CLEN) * NPROJ;
    float Ar = 1.0f, Ai = 0.0f, Hr = 0.0f, Hi = 0.0f;
    #pragma unroll 4
    for (int t = 0; t < CLEN; t++) {
        const float* row = base + (size_t)t * NPROJ;
        float ar = row[OFF_AR + d];
        float ai = row[OFF_AI + d];
        float k  = row[OFF_K + d];
        float v  = row[OFF_V + d];
        float acr, aci;
        make_ac(ar, ai, acr, aci);
        float kv = k * v;
        float nHr = acr * Hr - aci * Hi + kv;
        float nHi = acr * Hi + aci * Hr;
        Hr = nHr; Hi = nHi;
        float nAr = acr * Ar - aci * Ai;
        float nAi = acr * Ai + aci * Ar;
        Ar = nAr; Ai = nAi;
    }
    size_t o = ((size_t)(b * CHUNKS + c) * DD + d);
    g_cAr[o] = Ar; g_cAi[o] = Ai;
    g_cHr[o] = Hr; g_cHi[o] = Hi;
}

// ---------------- scan pass 2: sequential scan over chunk summaries ----------------
__global__ void __launch_bounds__(1024) scan_pass2() {
    int b = blockIdx.x;
    int d = threadIdx.x;
    float hr = 0.0f, hi = 0.0f;
    for (int c = 0; c < CHUNKS; c++) {
        size_t o = ((size_t)(b * CHUNKS + c) * DD + d);
        g_hinr[o] = hr; g_hini[o] = hi;
        float Ar = g_cAr[o], Ai = g_cAi[o];
        float Hr = g_cHr[o], Hi = g_cHi[o];
        float nr = Ar * hr - Ai * hi + Hr;
        float ni = Ar * hi + Ai * hr + Hi;
        hr = nr; hi = ni;
    }
}

// ---------------- scan pass 3: replay with carry + q gate + silu(g) ----------------
__global__ void __launch_bounds__(256) scan_pass3() {
    int d = blockIdx.x * 256 + threadIdx.x;
    int c = blockIdx.y;
    int b = blockIdx.z;
    size_t o = ((size_t)(b * CHUNKS + c) * DD + d);
    float hr = g_hinr[o], hi = g_hini[o];
    const float* base = g_proj + (size_t)(b * SS + c * CLEN) * NPROJ;
    float* ybase = g_y + (size_t)(b * SS + c * CLEN) * DD;
    #pragma unroll 4
    for (int t = 0; t < CLEN; t++) {
        const float* row = base + (size_t)t * NPROJ;
        float ar = row[OFF_AR + d];
        float ai = row[OFF_AI + d];
        float k  = row[OFF_K + d];
        float v  = row[OFF_V + d];
        float acr, aci;
        make_ac(ar, ai, acr, aci);
        float kv = k * v;
        float nhr = acr * hr - aci * hi + kv;
        float nhi = acr * hi + aci * hr;
        hr = nhr; hi = nhi;
        float q = row[OFF_Q + d];
        float g = row[OFF_G + d];
        float silu = g / (1.0f + __expf(-g));
        ybase[(size_t)t * DD + d] = q * hr * silu;
    }
}

// ---------------- launcher ----------------
extern "C" void kernel_launch(void* const* d_in, const int* in_sizes, int n_in,
                              void* d_out, int out_size) {
    const float* x  = (const float*)d_in[0];
    const float* wq = (const float*)d_in[1];
    const float* wk = (const float*)d_in[2];
    const float* wv = (const float*)d_in[3];
    const float* wa = (const float*)d_in[4];
    const float* wg = (const float*)d_in[5];
    const float* wo = (const float*)d_in[6];
    const float* rs = (const float*)d_in[7];
    float* out = (float*)d_out;

    float *xn, *proj, *y;
    cudaGetSymbolAddress((void**)&xn, g_xn);
    cudaGetSymbolAddress((void**)&proj, g_proj);
    cudaGetSymbolAddress((void**)&y, g_y);

    // 1. RMSNorm
    rmsnorm_kernel<<<MROWS, 256>>>(x, rs);

    // 2. Projections (tf32 wmma), all into the fused [M, 6144] buffer
    dim3 g1(DD / BN, MROWS / BM);       // 16 x 128
    dim3 ga(2 * DD / BN, MROWS / BM);   // 32 x 128 (wa is D x 2D)
    gemm_tf32<<<g1, 256>>>(xn, DD, wq, DD,     proj + OFF_Q,  NPROJ, DD);
    gemm_tf32<<<g1, 256>>>(xn, DD, wk, DD,     proj + OFF_K,  NPROJ, DD);
    gemm_tf32<<<g1, 256>>>(xn, DD, wv, DD,     proj + OFF_V,  NPROJ, DD);
    gemm_tf32<<<ga, 256>>>(xn, DD, wa, 2 * DD, proj + OFF_AR, NPROJ, DD);
    gemm_tf32<<<g1, 256>>>(xn, DD, wg, DD,     proj + OFF_G,  NPROJ, DD);

    // 3. Chunked associative scan (complex recurrence) + gating
    dim3 gs(DD / 256, CHUNKS, BB);
    scan_pass1<<<gs, 256>>>();
    scan_pass2<<<BB, DD>>>();
    scan_pass3<<<gs, 256>>>();

    // 4. Output projection
    gemm_tf32<<<g1, 256>>>(y, DD, wo, DD, out, DD, DD);
}

// round 4
// speedup vs baseline: 1.2101x; 1.2101x over previous
#include <cuda_runtime.h>
#include <mma.h>
#include <cstdint>

using namespace nvcuda;

// ---------------- problem constants ----------------
#define BB 4
#define SS 4096
#define DD 1024
#define MROWS (BB*SS)        // 16384
#define NPROJ 6144           // q|k|v|ar|ai|g
#define CHUNKS 64
#define CLEN 64
#define EPS 1e-6f

#define OFF_Q  0
#define OFF_K  1024
#define OFF_V  2048
#define OFF_AR 3072
#define OFF_AI 4096
#define OFF_G  5120

// ---------------- GEMM tiling ----------------
#define BM 128
#define BN 128
#define BK 16
#define KITERS (DD/BK)       // 64
#define LDA_S 20             // padded A row stride (floats)
#define LDB_S 132            // padded B row stride (floats)
#define ASTAGE (BM*LDA_S)    // 2560 floats
#define BSTAGE (BK*LDB_S)    // 2112 floats
#define NSTAGE 3
#define SMEM_BYTES (NSTAGE*(ASTAGE+BSTAGE)*4)   // 56064

// ---------------- scratch (device globals) ----------------
__device__ float g_xn[(size_t)MROWS * DD];
__device__ float g_proj[(size_t)MROWS * NPROJ];
__device__ float g_y[(size_t)MROWS * DD];
__device__ float g_wr[(size_t)DD * NPROJ];   // pre-rounded fused weights [1024,6144]
__device__ float g_wro[(size_t)DD * DD];     // pre-rounded wo
__device__ float g_cAr[BB * CHUNKS * DD];
__device__ float g_cAi[BB * CHUNKS * DD];
__device__ float g_cHr[BB * CHUNKS * DD];
__device__ float g_cHi[BB * CHUNKS * DD];
__device__ float g_hinr[BB * CHUNKS * DD];
__device__ float g_hini[BB * CHUNKS * DD];

// ---------------- helpers ----------------
__device__ __forceinline__ uint32_t smem_u32(const void* p) {
    uint32_t a;
    asm("{ .reg .u64 t; cvta.to.shared.u64 t, %1; cvt.u32.u64 %0, t; }" : "=r"(a) : "l"(p));
    return a;
}
__device__ __forceinline__ float tf32r(float x) {
    float y; asm("cvt.rna.tf32.f32 %0, %1;" : "=f"(y) : "f"(x)); return y;
}
__device__ __forceinline__ void cp16(void* dst, const void* src) {
    uint32_t d = smem_u32(dst);
    asm volatile("cp.async.cg.shared.global [%0], [%1], 16;" :: "r"(d), "l"(src));
}
#define CP_COMMIT() asm volatile("cp.async.commit_group;" ::: "memory")
#define CP_WAIT1()  asm volatile("cp.async.wait_group 1;" ::: "memory")

// ---------------- weight pre-round: src [1024, scols4*4] -> dst (pitch dpitch4), tf32 ----------------
__global__ void __launch_bounds__(256) preround_copy(const float4* __restrict__ src,
                                                     float4* __restrict__ dst,
                                                     int scols4, int dpitch4) {
    int i = blockIdx.x * 256 + threadIdx.x;
    int k = i / scols4;           // scols4 is a power of two (256 or 512)
    int c = i - k * scols4;
    float4 v = src[(size_t)k * scols4 + c];
    v.x = tf32r(v.x); v.y = tf32r(v.y); v.z = tf32r(v.z); v.w = tf32r(v.w);
    dst[(size_t)k * dpitch4 + c] = v;
}

// ---------------- RMSNorm: x -> g_xn (tf32-rounded) ----------------
__global__ void __launch_bounds__(256) rmsnorm_kernel(const float* __restrict__ x,
                                                      const float* __restrict__ scale) {
    int row = blockIdx.x;
    int tid = threadIdx.x;
    const float4* xr = (const float4*)(x + (size_t)row * DD);
    float4 v = xr[tid];
    float ss = v.x * v.x + v.y * v.y + v.z * v.z + v.w * v.w;
    #pragma unroll
    for (int o = 16; o; o >>= 1) ss += __shfl_xor_sync(0xffffffffu, ss, o);
    __shared__ float sbuf[8];
    if ((tid & 31) == 0) sbuf[tid >> 5] = ss;
    __syncthreads();
    if (tid < 8) {
        float t = sbuf[tid];
        #pragma unroll
        for (int o = 4; o; o >>= 1) t += __shfl_xor_sync(0xffu, t, o);
        if (tid == 0) sbuf[0] = t;
    }
    __syncthreads();
    float inv = rsqrtf(sbuf[0] * (1.0f / DD) + EPS);
    float4 sc = ((const float4*)scale)[tid];
    float4 o;
    o.x = tf32r(v.x * inv * sc.x);
    o.y = tf32r(v.y * inv * sc.y);
    o.z = tf32r(v.z * inv * sc.z);
    o.w = tf32r(v.w * inv * sc.w);
    ((float4*)(g_xn + (size_t)row * DD))[tid] = o;
}

// ---------------- tf32 GEMM with cp.async pipeline ----------------
// C[BMxBN tile] = A[M,1024] @ W[1024, ldwc];  ldc == ldw == ldwc
__global__ void __launch_bounds__(256, 2) gemm_tf32(const float* __restrict__ A,
                                                    const float* __restrict__ W,
                                                    float* __restrict__ C, int ldwc) {
    extern __shared__ float sm[];
    float* Abase = sm;
    float* Bbase = sm + NSTAGE * ASTAGE;

    int tid = threadIdx.x;
    int wid = tid >> 5;
    int wm = wid & 3;            // 4 warps along M (32 rows each)
    int wn = wid >> 2;           // 2 warps along N (64 cols each)
    int m0 = blockIdx.y * BM;
    int n0 = blockIdx.x * BN;

    const float* Ap = A + (size_t)m0 * DD;     // + k
    const float* Wp = W + n0;                  // + k*ldwc

    // stage loader: A tile BM x BK, B tile BK x BN
    auto load_stage = [&](int s, int kt) {
        float* As = Abase + s * ASTAGE;
        float* Bs = Bbase + s * BSTAGE;
        const float* Asrc = Ap + kt * BK;
        const float* Wsrc = Wp + (size_t)kt * BK * ldwc;
        #pragma unroll
        for (int i = 0; i < 2; i++) {
            int idx = tid + i * 256;           // 512 float4 for A
            int r = idx >> 2, c4 = idx & 3;
            cp16(As + r * LDA_S + c4 * 4, Asrc + (size_t)r * DD + c4 * 4);
        }
        #pragma unroll
        for (int i = 0; i < 2; i++) {
            int idx = tid + i * 256;           // 512 float4 for B
            int r = idx >> 5, c4 = idx & 31;
            cp16(Bs + r * LDB_S + c4 * 4, Wsrc + (size_t)r * ldwc + c4 * 4);
        }
    };

    wmma::fragment<wmma::accumulator, 16, 16, 8, float> acc[2][4];
    #pragma unroll
    for (int i = 0; i < 2; i++)
        #pragma unroll
        for (int j = 0; j < 4; j++)
            wmma::fill_fragment(acc[i][j], 0.0f);

    load_stage(0, 0); CP_COMMIT();
    load_stage(1, 1); CP_COMMIT();

    for (int kt = 0; kt < KITERS; kt++) {
        CP_WAIT1();
        __syncthreads();
        int s = kt % NSTAGE;
        const float* As = Abase + s * ASTAGE;
        const float* Bs = Bbase + s * BSTAGE;
        #pragma unroll
        for (int kk = 0; kk < BK; kk += 8) {
            wmma::fragment<wmma::matrix_a, 16, 16, 8, wmma::precision::tf32, wmma::row_major> af[2];
            wmma::fragment<wmma::matrix_b, 16, 16, 8, wmma::precision::tf32, wmma::row_major> bf[4];
            #pragma unroll
            for (int i = 0; i < 2; i++)
                wmma::load_matrix_sync(af[i], As + (wm * 32 + i * 16) * LDA_S + kk, LDA_S);
            #pragma unroll
            for (int j = 0; j < 4; j++)
                wmma::load_matrix_sync(bf[j], Bs + kk * LDB_S + wn * 64 + j * 16, LDB_S);
            #pragma unroll
            for (int i = 0; i < 2; i++)
                #pragma unroll
                for (int j = 0; j < 4; j++)
                    wmma::mma_sync(acc[i][j], af[i], bf[j], acc[i][j]);
        }
        int kn = kt + 2;
        if (kn < KITERS) load_stage(kn % NSTAGE, kn);
        CP_COMMIT();
    }

    #pragma unroll
    for (int i = 0; i < 2; i++)
        #pragma unroll
        for (int j = 0; j < 4; j++)
            wmma::store_matrix_sync(
                C + (size_t)(m0 + wm * 32 + i * 16) * ldwc + n0 + wn * 64 + j * 16,
                acc[i][j], ldwc, wmma::mem_row_major);
}

// ---------------- complex gate helper ----------------
__device__ __forceinline__ void make_ac(float ar, float ai, float& acr, float& aci) {
    float r = sqrtf(ar * ar + ai * ai);
    float s = 1.0f / (1.0f + __expf(-r));
    if (r > 0.0f) {
        float inv = s / r;
        acr = ar * inv;
        aci = ai * inv;
    } else {
        acr = s;
        aci = 0.0f;
    }
}

// ---------------- scan pass 1: per-chunk summaries ----------------
__global__ void __launch_bounds__(256) scan_pass1() {
    int d = blockIdx.x * 256 + threadIdx.x;
    int c = blockIdx.y;
    int b = blockIdx.z;
    const float* bse = g_proj + (size_t)(b * SS + c * CLEN) * NPROJ;
    float Ar = 1.0f, Ai = 0.0f, Hr = 0.0f, Hi = 0.0f;
    #pragma unroll 4
    for (int t = 0; t < CLEN; t++) {
        const float* row = bse + (size_t)t * NPROJ;
        float ar = row[OFF_AR + d];
        float ai = row[OFF_AI + d];
        float k  = row[OFF_K + d];
        float v  = row[OFF_V + d];
        float acr, aci;
        make_ac(ar, ai, acr, aci);
        float kv = k * v;
        float nHr = acr * Hr - aci * Hi + kv;
        float nHi = acr * Hi + aci * Hr;
        Hr = nHr; Hi = nHi;
        float nAr = acr * Ar - aci * Ai;
        float nAi = acr * Ai + aci * Ar;
        Ar = nAr; Ai = nAi;
    }
    size_t o = ((size_t)(b * CHUNKS + c) * DD + d);
    g_cAr[o] = Ar; g_cAi[o] = Ai;
    g_cHr[o] = Hr; g_cHi[o] = Hi;
}

// ---------------- scan pass 2 ----------------
__global__ void __launch_bounds__(1024) scan_pass2() {
    int b = blockIdx.x;
    int d = threadIdx.x;
    float hr = 0.0f, hi = 0.0f;
    for (int c = 0; c < CHUNKS; c++) {
        size_t o = ((size_t)(b * CHUNKS + c) * DD + d);
        g_hinr[o] = hr; g_hini[o] = hi;
        float Ar = g_cAr[o], Ai = g_cAi[o];
        float Hr = g_cHr[o], Hi = g_cHi[o];
        float nr = Ar * hr - Ai * hi + Hr;
        float ni = Ar * hi + Ai * hr + Hi;
        hr = nr; hi = ni;
    }
}

// ---------------- scan pass 3: replay + gates (tf32-rounded output) ----------------
__global__ void __launch_bounds__(256) scan_pass3() {
    int d = blockIdx.x * 256 + threadIdx.x;
    int c = blockIdx.y;
    int b = blockIdx.z;
    size_t o = ((size_t)(b * CHUNKS + c) * DD + d);
    float hr = g_hinr[o], hi = g_hini[o];
    const float* bse = g_proj + (size_t)(b * SS + c * CLEN) * NPROJ;
    float* ybase = g_y + (size_t)(b * SS + c * CLEN) * DD;
    #pragma unroll 4
    for (int t = 0; t < CLEN; t++) {
        const float* row = bse + (size_t)t * NPROJ;
        float ar = row[OFF_AR + d];
        float ai = row[OFF_AI + d];
        float k  = row[OFF_K + d];
        float v  = row[OFF_V + d];
        float acr, aci;
        make_ac(ar, ai, acr, aci);
        float kv = k * v;
        float nhr = acr * hr - aci * hi + kv;
        float nhi = acr * hi + aci * hr;
        hr = nhr; hi = nhi;
        float q = row[OFF_Q + d];
        float g = row[OFF_G + d];
        float silu = g / (1.0f + __expf(-g));
        ybase[(size_t)t * DD + d] = tf32r(q * hr * silu);
    }
}

// ---------------- launcher ----------------
extern "C" void kernel_launch(void* const* d_in, const int* in_sizes, int n_in,
                              void* d_out, int out_size) {
    const float* x  = (const float*)d_in[0];
    const float* wq = (const float*)d_in[1];
    const float* wk = (const float*)d_in[2];
    const float* wv = (const float*)d_in[3];
    const float* wa = (const float*)d_in[4];
    const float* wg = (const float*)d_in[5];
    const float* wo = (const float*)d_in[6];
    const float* rs = (const float*)d_in[7];
    float* out = (float*)d_out;

    float *xn, *proj, *y, *wr, *wro;
    cudaGetSymbolAddress((void**)&xn,  g_xn);
    cudaGetSymbolAddress((void**)&proj, g_proj);
    cudaGetSymbolAddress((void**)&y,   g_y);
    cudaGetSymbolAddress((void**)&wr,  g_wr);
    cudaGetSymbolAddress((void**)&wro, g_wro);

    cudaFuncSetAttribute(gemm_tf32, cudaFuncAttributeMaxDynamicSharedMemorySize, SMEM_BYTES);

    // 1. Pre-round weights into fused [1024, 6144] buffer (tf32)
    preround_copy<<<1024, 256>>>((const float4*)wq, (float4*)(wr) + 0,    256, 1536);
    preround_copy<<<1024, 256>>>((const float4*)wk, (float4*)(wr) + 256,  256, 1536);
    preround_copy<<<1024, 256>>>((const float4*)wv, (float4*)(wr) + 512,  256, 1536);
    preround_copy<<<2048, 256>>>((const float4*)wa, (float4*)(wr) + 768,  512, 1536);
    preround_copy<<<1024, 256>>>((const float4*)wg, (float4*)(wr) + 1280, 256, 1536);
    preround_copy<<<1024, 256>>>((const float4*)wo, (float4*)(wro),       256, 256);

    // 2. RMSNorm (tf32-rounded output)
    rmsnorm_kernel<<<MROWS, 256>>>(x, rs);

    // 3. Fused projection GEMM: [16384,1024] @ [1024,6144]
    gemm_tf32<<<dim3(NPROJ / BN, MROWS / BM), 256, SMEM_BYTES>>>(xn, wr, proj, NPROJ);

    // 4. Chunked associative scan + gating
    dim3 gs(DD / 256, CHUNKS, BB);
    scan_pass1<<<gs, 256>>>();
    scan_pass2<<<BB, DD>>>();
    scan_pass3<<<gs, 256>>>();

    // 5. Output projection: [16384,1024] @ [1024,1024]
    gemm_tf32<<<dim3(DD / BN, MROWS / BM), 256, SMEM_BYTES>>>(y, wro, out, DD);
}

// round 9
// speedup vs baseline: 4.0034x; 3.3083x over previous
#include <cuda_runtime.h>
#include <cuda_fp16.h>
#include <mma.h>
#include <cstdint>

using namespace nvcuda;

// ---------------- problem constants ----------------
#define BB 4
#define SS 4096
#define DD 1024
#define MROWS (BB*SS)        // 16384
#define NPROJ 6144           // q|k|v|ar|ai|g
#define CHUNKS 64
#define CLEN 64
#define EPS 1e-6f

#define OFF_Q  0
#define OFF_K  1024
#define OFF_V  2048
#define OFF_AR 3072
#define OFF_AI 4096
#define OFF_G  5120

// ---------------- GEMM tiling (fp16 operands, fp32 accum) ----------------
#define BM 128
#define BN 128
#define BK 32                // halfs per K chunk
#define KITERS (DD/BK)       // 32
#define LDA_S 40             // padded A row stride (halfs)
#define LDB_S 136            // padded B row stride (halfs)
#define ASTAGE (BM*LDA_S)    // 5120 halfs
#define BSTAGE (BK*LDB_S)    // 4352 halfs
#define NSTAGE 3
#define SMEM_BYTES (NSTAGE*(ASTAGE+BSTAGE)*2)   // 56832 B

// ---------------- scratch (device globals) ----------------
__device__ __half g_xnh[(size_t)MROWS * DD];      // 32 MB
__device__ float  g_proj[(size_t)MROWS * NPROJ];  // 384 MB
__device__ __half g_yh[(size_t)MROWS * DD];       // 32 MB
__device__ __half g_wr[(size_t)DD * NPROJ];       // fused weights fp16 [1024,6144]
__device__ __half g_wro[(size_t)DD * DD];
__device__ float g_cAr[BB * CHUNKS * DD];
__device__ float g_cAi[BB * CHUNKS * DD];
__device__ float g_cHr[BB * CHUNKS * DD];
__device__ float g_cHi[BB * CHUNKS * DD];
__device__ float g_hinr[BB * CHUNKS * DD];
__device__ float g_hini[BB * CHUNKS * DD];

// ---------------- helpers ----------------
__device__ __forceinline__ uint32_t smem_u32(const void* p) {
    uint32_t a;
    asm("{ .reg .u64 t; cvta.to.shared.u64 t, %1; cvt.u32.u64 %0, t; }" : "=r"(a) : "l"(p));
    return a;
}
__device__ __forceinline__ void cp16(void* dst, const void* src) {
    uint32_t d = smem_u32(dst);
    asm volatile("cp.async.cg.shared.global [%0], [%1], 16;" :: "r"(d), "l"(src));
}
#define CP_COMMIT() asm volatile("cp.async.commit_group;" ::: "memory")
#define CP_WAIT1()  asm volatile("cp.async.wait_group 1;" ::: "memory")

__device__ __forceinline__ uint2 f4_to_h4(float4 v) {
    __half2 lo = __floats2half2_rn(v.x, v.y);
    __half2 hi = __floats2half2_rn(v.z, v.w);
    uint2 r;
    r.x = *(uint32_t*)&lo;
    r.y = *(uint32_t*)&hi;
    return r;
}

// ---------------- weight convert: float [1024, scols4*4] -> half (pitch dpitch halfs) ----------------
__global__ void __launch_bounds__(256) w_to_half(const float4* __restrict__ src,
                                                 __half* __restrict__ dst,
                                                 int scols4, int dpitch) {
    int i = blockIdx.x * 256 + threadIdx.x;
    int k = i / scols4;
    int c = i - k * scols4;
    float4 v = src[(size_t)k * scols4 + c];
    *(uint2*)(dst + (size_t)k * dpitch + c * 4) = f4_to_h4(v);
}

// ---------------- RMSNorm: x -> g_xnh (half) ----------------
__global__ void __launch_bounds__(256) rmsnorm_kernel(const float* __restrict__ x,
                                                      const float* __restrict__ scale) {
    int row = blockIdx.x;
    int tid = threadIdx.x;
    const float4* xr = (const float4*)(x + (size_t)row * DD);
    float4 v = xr[tid];
    float ss = v.x * v.x + v.y * v.y + v.z * v.z + v.w * v.w;
    #pragma unroll
    for (int o = 16; o; o >>= 1) ss += __shfl_xor_sync(0xffffffffu, ss, o);
    __shared__ float sbuf[8];
    if ((tid & 31) == 0) sbuf[tid >> 5] = ss;
    __syncthreads();
    if (tid < 8) {
        float t = sbuf[tid];
        #pragma unroll
        for (int o = 4; o; o >>= 1) t += __shfl_xor_sync(0xffu, t, o);
        if (tid == 0) sbuf[0] = t;
    }
    __syncthreads();
    float inv = rsqrtf(sbuf[0] * (1.0f / DD) + EPS);
    float4 sc = ((const float4*)scale)[tid];
    float4 o;
    o.x = v.x * inv * sc.x;
    o.y = v.y * inv * sc.y;
    o.z = v.z * inv * sc.z;
    o.w = v.w * inv * sc.w;
    *(uint2*)(g_xnh + (size_t)row * DD + tid * 4) = f4_to_h4(o);
}

// ---------------- fp16 GEMM with cp.async pipeline ----------------
// C[BMxBN tile] (float) = A[M,1024](half) @ W[1024, ldwc](half)
__global__ void __launch_bounds__(256, 2) gemm_fp16(const __half* __restrict__ A,
                                                    const __half* __restrict__ W,
                                                    float* __restrict__ C, int ldwc) {
    extern __shared__ __half sm[];
    __half* Abase = sm;
    __half* Bbase = sm + NSTAGE * ASTAGE;

    int tid = threadIdx.x;
    int wid = tid >> 5;
    int wm = wid & 3;            // 4 warps along M (32 rows each)
    int wn = wid >> 2;           // 2 warps along N (64 cols each)
    int m0 = blockIdx.y * BM;
    int n0 = blockIdx.x * BN;

    const __half* Ap = A + (size_t)m0 * DD;
    const __half* Wp = W + n0;

    auto load_stage = [&](int s, int kt) {
        __half* As = Abase + s * ASTAGE;
        __half* Bs = Bbase + s * BSTAGE;
        const __half* Asrc = Ap + kt * BK;
        const __half* Wsrc = Wp + (size_t)kt * BK * ldwc;
        #pragma unroll
        for (int i = 0; i < 2; i++) {
            int idx = tid + i * 256;           // 512 16B-chunks for A (128 rows x 4)
            int r = idx >> 2, c8 = idx & 3;
            cp16(As + r * LDA_S + c8 * 8, Asrc + (size_t)r * DD + c8 * 8);
        }
        #pragma unroll
        for (int i = 0; i < 2; i++) {
            int idx = tid + i * 256;           // 512 16B-chunks for B (32 rows x 16)
            int r = idx >> 4, c8 = idx & 15;
            cp16(Bs + r * LDB_S + c8 * 8, Wsrc + (size_t)r * ldwc + c8 * 8);
        }
    };

    wmma::fragment<wmma::accumulator, 16, 16, 16, float> acc[2][4];
    #pragma unroll
    for (int i = 0; i < 2; i++)
        #pragma unroll
        for (int j = 0; j < 4; j++)
            wmma::fill_fragment(acc[i][j], 0.0f);

    load_stage(0, 0); CP_COMMIT();
    load_stage(1, 1); CP_COMMIT();

    for (int kt = 0; kt < KITERS; kt++) {
        CP_WAIT1();
        __syncthreads();
        int s = kt % NSTAGE;
        const __half* As = Abase + s * ASTAGE;
        const __half* Bs = Bbase + s * BSTAGE;
        #pragma unroll
        for (int kk = 0; kk < BK; kk += 16) {
            wmma::fragment<wmma::matrix_a, 16, 16, 16, __half, wmma::row_major> af[2];
            wmma::fragment<wmma::matrix_b, 16, 16, 16, __half, wmma::row_major> bf[4];
            #pragma unroll
            for (int i = 0; i < 2; i++)
                wmma::load_matrix_sync(af[i], As + (wm * 32 + i * 16) * LDA_S + kk, LDA_S);
            #pragma unroll
            for (int j = 0; j < 4; j++)
                wmma::load_matrix_sync(bf[j], Bs + kk * LDB_S + wn * 64 + j * 16, LDB_S);
            #pragma unroll
            for (int i = 0; i < 2; i++)
                #pragma unroll
                for (int j = 0; j < 4; j++)
                    wmma::mma_sync(acc[i][j], af[i], bf[j], acc[i][j]);
        }
        int kn = kt + 2;
        if (kn < KITERS) load_stage(kn % NSTAGE, kn);
        CP_COMMIT();
    }

    #pragma unroll
    for (int i = 0; i < 2; i++)
        #pragma unroll
        for (int j = 0; j < 4; j++)
            wmma::store_matrix_sync(
                C + (size_t)(m0 + wm * 32 + i * 16) * ldwc + n0 + wn * 64 + j * 16,
                acc[i][j], ldwc, wmma::mem_row_major);
}

// ---------------- complex gate helper ----------------
__device__ __forceinline__ void make_ac(float ar, float ai, float& acr, float& aci) {
    float r = sqrtf(ar * ar + ai * ai);
    float s = 1.0f / (1.0f + __expf(-r));
    if (r > 0.0f) {
        float inv = s / r;
        acr = ar * inv;
        aci = ai * inv;
    } else {
        acr = s;
        aci = 0.0f;
    }
}

// ---------------- scan pass 1: per-chunk summaries ----------------
__global__ void __launch_bounds__(256) scan_pass1() {
    int d = blockIdx.x * 256 + threadIdx.x;
    int c = blockIdx.y;
    int b = blockIdx.z;
    const float* bse = g_proj + (size_t)(b * SS + c * CLEN) * NPROJ;
    float Ar = 1.0f, Ai = 0.0f, Hr = 0.0f, Hi = 0.0f;
    #pragma unroll 4
    for (int t = 0; t < CLEN; t++) {
        const float* row = bse + (size_t)t * NPROJ;
        float ar = row[OFF_AR + d];
        float ai = row[OFF_AI + d];
        float k  = row[OFF_K + d];
        float v  = row[OFF_V + d];
        float acr, aci;
        make_ac(ar, ai, acr, aci);
        float kv = k * v;
        float nHr = acr * Hr - aci * Hi + kv;
        float nHi = acr * Hi + aci * Hr;
        Hr = nHr; Hi = nHi;
        float nAr = acr * Ar - aci * Ai;
        float nAi = acr * Ai + aci * Ar;
        Ar = nAr; Ai = nAi;
    }
    size_t o = ((size_t)(b * CHUNKS + c) * DD + d);
    g_cAr[o] = Ar; g_cAi[o] = Ai;
    g_cHr[o] = Hr; g_cHi[o] = Hi;
}

// ---------------- scan pass 2 ----------------
__global__ void __launch_bounds__(1024) scan_pass2() {
    int b = blockIdx.x;
    int d = threadIdx.x;
    float hr = 0.0f, hi = 0.0f;
    for (int c = 0; c < CHUNKS; c++) {
        size_t o = ((size_t)(b * CHUNKS + c) * DD + d);
        g_hinr[o] = hr; g_hini[o] = hi;
        float Ar = g_cAr[o], Ai = g_cAi[o];
        float Hr = g_cHr[o], Hi = g_cHi[o];
        float nr = Ar * hr - Ai * hi + Hr;
        float ni = Ar * hi + Ai * hr + Hi;
        hr = nr; hi = ni;
    }
}

// ---------------- scan pass 3: replay + gates -> g_yh (half) ----------------
__global__ void __launch_bounds__(256) scan_pass3() {
    int d = blockIdx.x * 256 + threadIdx.x;
    int c = blockIdx.y;
    int b = blockIdx.z;
    size_t o = ((size_t)(b * CHUNKS + c) * DD + d);
    float hr = g_hinr[o], hi = g_hini[o];
    const float* bse = g_proj + (size_t)(b * SS + c * CLEN) * NPROJ;
    __half* ybase = g_yh + (size_t)(b * SS + c * CLEN) * DD;
    #pragma unroll 4
    for (int t = 0; t < CLEN; t++) {
        const float* row = bse + (size_t)t * NPROJ;
        float ar = row[OFF_AR + d];
        float ai = row[OFF_AI + d];
        float k  = row[OFF_K + d];
        float v  = row[OFF_V + d];
        float acr, aci;
        make_ac(ar, ai, acr, aci);
        float kv = k * v;
        float nhr = acr * hr - aci * hi + kv;
        float nhi = acr * hi + aci * hr;
        hr = nhr; hi = nhi;
        float q = row[OFF_Q + d];
        float g = row[OFF_G + d];
        float silu = g / (1.0f + __expf(-g));
        ybase[(size_t)t * DD + d] = __float2half_rn(q * hr * silu);
    }
}

// ---------------- launcher ----------------
extern "C" void kernel_launch(void* const* d_in, const int* in_sizes, int n_in,
                              void* d_out, int out_size) {
    const float* x  = (const float*)d_in[0];
    const float* wq = (const float*)d_in[1];
    const float* wk = (const float*)d_in[2];
    const float* wv = (const float*)d_in[3];
    const float* wa = (const float*)d_in[4];
    const float* wg = (const float*)d_in[5];
    const float* wo = (const float*)d_in[6];
    const float* rs = (const float*)d_in[7];
    float* out = (float*)d_out;

    __half *xnh, *yh, *wr, *wro;
    float *proj;
    cudaGetSymbolAddress((void**)&xnh, g_xnh);
    cudaGetSymbolAddress((void**)&proj, g_proj);
    cudaGetSymbolAddress((void**)&yh,  g_yh);
    cudaGetSymbolAddress((void**)&wr,  g_wr);
    cudaGetSymbolAddress((void**)&wro, g_wro);

    cudaFuncSetAttribute(gemm_fp16, cudaFuncAttributeMaxDynamicSharedMemorySize, SMEM_BYTES);

    // 1. Convert weights into fused fp16 [1024, 6144] buffer
    w_to_half<<<1024, 256>>>((const float4*)wq, wr + 0,    256, NPROJ);
    w_to_half<<<1024, 256>>>((const float4*)wk, wr + 1024, 256, NPROJ);
    w_to_half<<<1024, 256>>>((const float4*)wv, wr + 2048, 256, NPROJ);
    w_to_half<<<2048, 256>>>((const float4*)wa, wr + 3072, 512, NPROJ);
    w_to_half<<<1024, 256>>>((const float4*)wg, wr + 5120, 256, NPROJ);
    w_to_half<<<1024, 256>>>((const float4*)wo, wro,       256, DD);

    // 2. RMSNorm (fp16 output)
    rmsnorm_kernel<<<MROWS, 256>>>(x, rs);

    // 3. Fused projection GEMM: [16384,1024] @ [1024,6144] (fp16 in, fp32 out)
    gemm_fp16<<<dim3(NPROJ / BN, MROWS / BM), 256, SMEM_BYTES>>>(xnh, wr, proj, NPROJ);

    // 4. Chunked associative scan + gating
    dim3 gs(DD / 256, CHUNKS, BB);
    scan_pass1<<<gs, 256>>>();
    scan_pass2<<<BB, DD>>>();
    scan_pass3<<<gs, 256>>>();

    // 5. Output projection: [16384,1024] @ [1024,1024]
    gemm_fp16<<<dim3(DD / BN, MROWS / BM), 256, SMEM_BYTES>>>(yh, wro, out, DD);
}